// round 8
// baseline (speedup 1.0000x reference)
#include <cuda_runtime.h>

// Problem constants (fixed by setup_inputs):
// x_0  : [128, 64, 16] f32   (d_in[0])
// x_h  : [128, 64, 16] f32   (d_in[1], UNUSED — reference bug recomputes from x_0)
// Vm   : [64, 1, 64, 16] f32 (d_in[2])
// Vh   : [64, 1, 16, 64] f32 (d_in[3])
// out  : [128, 64, 16] f32
//
// out[b,k,d] = sum_v ( sum_i x0[b,i,d]*Vm[k,i,v] ) * ( sum_j x0flat[b,64d+j]*Vh[k,v,j] )
//
// Phase-split: warp = (side, k). A-warps contract over i with Vm, B-warps over j
// with Vh^T. lane = (r,h): rows 8r..8r+7, v-half h. 64B smem traffic per FFMA2
// (crossbar/FMA balanced). Partials exchanged via smem, dot in phase 3.

#define NTHR 256
#define KG   4   // k per CTA
#define BBLK 8   // batches per CTA (128 output rows)

// ---- packed f32x2 helpers ----
__device__ __forceinline__ unsigned long long pack2(float x) {
    unsigned long long r;
    asm("mov.b64 %0, {%1, %1};" : "=l"(r) : "f"(x));
    return r;
}
__device__ __forceinline__ void fma2(unsigned long long& d,
                                     unsigned long long a,
                                     unsigned long long b) {
    asm("fma.rn.f32x2 %0, %1, %2, %0;" : "+l"(d) : "l"(a), "l"(b));
}
__device__ __forceinline__ void lds_2x64(unsigned long long& p0,
                                         unsigned long long& p1,
                                         unsigned addr) {
    asm("ld.shared.v2.u64 {%0, %1}, [%2];" : "=l"(p0), "=l"(p1) : "r"(addr));
}
__device__ __forceinline__ void lds_f4(float& a, float& b, float& c, float& d,
                                       unsigned addr) {
    asm("ld.shared.v4.f32 {%0, %1, %2, %3}, [%4];"
        : "=f"(a), "=f"(b), "=f"(c), "=f"(d) : "r"(addr));
}
__device__ __forceinline__ void sts_f4(unsigned addr, float a, float b, float c, float d) {
    asm("st.shared.v4.f32 [%0], {%1, %2, %3, %4};"
        :: "r"(addr), "f"(a), "f"(b), "f"(c), "f"(d));
}
__device__ __forceinline__ void unpack2(float& lo, float& hi, unsigned long long p) {
    asm("mov.b64 {%0, %1}, %2;" : "=f"(lo), "=f"(hi) : "l"(p));
}

// Dynamic SMEM layout (floats):
//  Phase 1/2 (staging + compute):
//   Xa  [    0,  8192)  Xa[i*128 + row] = x0[(bbase+row/16)*1024 + i*16 + row%16]
//   Xb  [ 8192, 16384)  Xb[j*128 + row] = x0[(bbase+row/16)*1024 + (row%16)*64 + j]
//   VmS [16384, 20480)  VmS[q*1024 + i*16 + v] = Vm[(k0+q)*1024 + i*16 + v]
//   VhT [20480, 24576)  VhT[q*1024 + j*16 + v] = Vh[(k0+q)*1024 + v*64 + j]
//  Phase 3 (after sync, overwrites Xa/Xb):
//   A_s [    0,  8192)  A_s[pa*128 + row], pa = (k*2+h)*8 + v'   (v = h*8+v')
//   B_s [ 8192, 16384)  same layout
#define SMEM_FLOATS 24576
#define SMEM_BYTES  (SMEM_FLOATS * 4)

__global__ void __launch_bounds__(NTHR, 2)
cin_kernel(const float* __restrict__ x0,
           const float* __restrict__ Vm,
           const float* __restrict__ Vh,
           float* __restrict__ out)
{
    extern __shared__ __align__(16) float smem[];
    float* Xa  = smem;
    float* Xb  = smem + 8192;
    float* VmS = smem + 16384;
    float* VhT = smem + 20480;

    const int tid   = threadIdx.x;
    const int k0    = blockIdx.x * KG;   // 16 k-groups
    const int bbase = blockIdx.y * BBLK; // 16 b-groups

    // ---- stage VmS: 4 consecutive k tiles = 4096 contiguous floats ----
    {
        const float4* src = reinterpret_cast<const float4*>(Vm + k0 * 1024);
        float4* dst = reinterpret_cast<float4*>(VmS);
        #pragma unroll
        for (int r = 0; r < 4; r++) dst[tid + r * NTHR] = src[tid + r * NTHR];
    }
    // ---- stage VhT: transpose Vh[k][v][j] -> VhT[q][j][v] ----
    {
        #pragma unroll
        for (int r = 0; r < 16; r++) {
            int idx = tid + r * NTHR;            // 0..4095
            int q   = idx >> 10;
            int rem = idx & 1023;
            int j   = rem >> 4;
            int v   = rem & 15;
            VhT[idx] = Vh[(k0 + q) * 1024 + v * 64 + j];
        }
    }
    // ---- stage Xa: Xa[i*128 + bl*16 + d] = x0[b][i][d]  (float4 both sides) ----
    {
        #pragma unroll
        for (int r = 0; r < 8; r++) {
            int idx = tid + r * NTHR;            // 0..2047 float4s
            int d4  = idx & 3;
            int bl  = (idx >> 2) & 7;
            int i   = idx >> 5;
            float4 w = *reinterpret_cast<const float4*>(
                x0 + (bbase + bl) * 1024 + i * 16 + d4 * 4);
            *reinterpret_cast<float4*>(&Xa[i * 128 + bl * 16 + d4 * 4]) = w;
        }
    }
    // ---- stage Xb: Xb[j*128 + bl*16 + d] = x0flat[b][d*64 + j] (float4 reads) ----
    {
        #pragma unroll
        for (int r = 0; r < 8; r++) {
            int idx = tid + r * NTHR;            // 0..2047
            int bl  = idx >> 8;
            int j4  = (idx >> 4) & 15;
            int d   = idx & 15;
            float4 w = *reinterpret_cast<const float4*>(
                x0 + (bbase + bl) * 1024 + d * 64 + j4 * 4);
            int base = (j4 * 4) * 128 + bl * 16 + d;
            Xb[base      ] = w.x;
            Xb[base + 128] = w.y;
            Xb[base + 256] = w.z;
            Xb[base + 384] = w.w;
        }
    }
    __syncthreads();

    const unsigned smem_b = (unsigned)__cvta_generic_to_shared(smem);

    // warp w: side = w>>2 (0 = A via Xa/VmS, 1 = B via Xb/VhT), q = w&3 -> k = k0+q
    // lane: r = lane>>1 (rows 8r..8r+7), h = lane&1 (v-half)
    const int w    = tid >> 5;
    const int lane = tid & 31;
    const int side = w >> 2;
    const int q    = w & 3;
    const int r    = lane >> 1;
    const int h    = lane & 1;

    const unsigned x_base = smem_b + (unsigned)(side * 8192 * 4) + (unsigned)(r * 32);
    const unsigned v_base = smem_b + (unsigned)((16384 + side * 4096) * 4)
                                   + (unsigned)(q * 4096 + h * 32);

    unsigned long long A[8][4];
    #pragma unroll
    for (int t = 0; t < 8; t++)
        #pragma unroll
        for (int p = 0; p < 4; p++) A[t][p] = 0ull;

    // ---- phase 2: contract over 64 indices ----
    #pragma unroll 1
    for (int i = 0; i < 64; i++) {
        float x[8];
        unsigned xaddr = x_base + (unsigned)(i * 512);
        lds_f4(x[0], x[1], x[2], x[3], xaddr);
        lds_f4(x[4], x[5], x[6], x[7], xaddr + 16u);
        unsigned long long p0, p1, p2, p3;
        unsigned vaddr = v_base + (unsigned)(i * 64);
        lds_2x64(p0, p1, vaddr);
        lds_2x64(p2, p3, vaddr + 16u);
        #pragma unroll
        for (int t = 0; t < 8; t++) {
            unsigned long long xp = pack2(x[t]);
            fma2(A[t][0], xp, p0);
            fma2(A[t][1], xp, p1);
            fma2(A[t][2], xp, p2);
            fma2(A[t][3], xp, p3);
        }
    }

    __syncthreads();  // everyone done reading Xa/Xb/V before overwriting

    // ---- write partials: side region base + plane pa = (q*2+h)*8 + v' ----
    {
        unsigned obase = smem_b + (unsigned)(side * 8192 * 4)
                                + (unsigned)(((q * 2 + h) * 8) * 512)
                                + (unsigned)(r * 32);
        #pragma unroll
        for (int p = 0; p < 4; p++) {
            float l[8], hh[8];
            #pragma unroll
            for (int t = 0; t < 8; t++) unpack2(l[t], hh[t], A[t][p]);
            unsigned a0 = obase + (unsigned)((2 * p) * 512);
            sts_f4(a0,        l[0], l[1], l[2], l[3]);
            sts_f4(a0 + 16u,  l[4], l[5], l[6], l[7]);
            unsigned a1 = obase + (unsigned)((2 * p + 1) * 512);
            sts_f4(a1,        hh[0], hh[1], hh[2], hh[3]);
            sts_f4(a1 + 16u,  hh[4], hh[5], hh[6], hh[7]);
        }
    }

    __syncthreads();

    // ---- phase 3: out[row, k] = sum_v A_s * B_s  (conflict-free LDS.32) ----
    {
        const int row = tid & 127;
        const int kk  = tid >> 7;  // 0..1
        const float* As = smem;
        const float* Bs = smem + 8192;
        #pragma unroll
        for (int kx = 0; kx < 2; kx++) {
            int k = kk + kx * 2;
            float s = 0.f;
            #pragma unroll
            for (int pa = 0; pa < 16; pa++) {
                int off = (k * 16 + pa) * 128 + row;
                s = fmaf(As[off], Bs[off], s);
            }
            out[(bbase + (row >> 4)) * 1024 + (k0 + k) * 16 + (row & 15)] = s;
        }
    }
}

extern "C" void kernel_launch(void* const* d_in, const int* in_sizes, int n_in,
                              void* d_out, int out_size) {
    (void)in_sizes; (void)n_in; (void)out_size;
    const float* x0 = (const float*)d_in[0];
    // d_in[1] (x_h) intentionally unused: reference recomputes it from x_0.
    const float* Vm = (const float*)d_in[2];
    const float* Vh = (const float*)d_in[3];
    float* out = (float*)d_out;

    cudaFuncSetAttribute(cin_kernel,
                         cudaFuncAttributeMaxDynamicSharedMemorySize, SMEM_BYTES);

    dim3 grid(64 / KG, 128 / BBLK);  // (16 k-groups, 16 b-groups) = 256 CTAs
    cin_kernel<<<grid, NTHR, SMEM_BYTES>>>(x0, Vm, Vh, out);
}

// round 9
// speedup vs baseline: 1.0102x; 1.0102x over previous
#include <cuda_runtime.h>

// Problem constants (fixed by setup_inputs):
// x_0  : [128, 64, 16] f32   (d_in[0])
// x_h  : [128, 64, 16] f32   (d_in[1], UNUSED — reference bug recomputes from x_0)
// Vm   : [64, 1, 64, 16] f32 (d_in[2])
// Vh   : [64, 1, 16, 64] f32 (d_in[3])
// out  : [128, 64, 16] f32
//
// out[b,k,d] = sum_v ( sum_i x0[b,i,d]*Vm[k,i,v] ) * ( sum_j x0flat[b,64d+j]*Vh[k,v,j] )
//
// Warp = (side, k-pair). Lane = (u = 8-row group, h = v-half); each lane
// accumulates 8 rows x 8 v x 2 k = 64 u64 (f32x2 over v-pairs).
// Per iter: 2 LDS.128 (x, 8 rows) + 4 LDS.128 (V, 8 v-pairs x 2 k) -> 64 FFMA2.
// 48B smem writeback per FFMA2. Partials exchanged via smem as u64, dot in phase 3.

#define NTHR 128
#define KG   4   // k per CTA
#define BBLK 8   // batches per CTA (128 output rows)

// ---- packed f32x2 helpers ----
__device__ __forceinline__ unsigned long long pack2(float x) {
    unsigned long long r;
    asm("mov.b64 %0, {%1, %1};" : "=l"(r) : "f"(x));
    return r;
}
__device__ __forceinline__ void fma2(unsigned long long& d,
                                     unsigned long long a,
                                     unsigned long long b) {
    asm("fma.rn.f32x2 %0, %1, %2, %0;" : "+l"(d) : "l"(a), "l"(b));
}
__device__ __forceinline__ void mul2(unsigned long long& d,
                                     unsigned long long a,
                                     unsigned long long b) {
    asm("mul.rn.f32x2 %0, %1, %2;" : "=l"(d) : "l"(a), "l"(b));
}
__device__ __forceinline__ void lds_2x64(unsigned long long& p0,
                                         unsigned long long& p1,
                                         unsigned addr) {
    asm("ld.shared.v2.u64 {%0, %1}, [%2];" : "=l"(p0), "=l"(p1) : "r"(addr));
}
__device__ __forceinline__ void lds_f4(float& a, float& b, float& c, float& d,
                                       unsigned addr) {
    asm("ld.shared.v4.f32 {%0, %1, %2, %3}, [%4];"
        : "=f"(a), "=f"(b), "=f"(c), "=f"(d) : "r"(addr));
}
__device__ __forceinline__ void sts_2x64(unsigned addr,
                                         unsigned long long a,
                                         unsigned long long b) {
    asm("st.shared.v2.u64 [%0], {%1, %2};" :: "r"(addr), "l"(a), "l"(b));
}
__device__ __forceinline__ unsigned long long lds_u64(unsigned addr) {
    unsigned long long r;
    asm("ld.shared.u64 %0, [%1];" : "=l"(r) : "r"(addr));
    return r;
}
__device__ __forceinline__ void unpack2(float& lo, float& hi, unsigned long long p) {
    asm("mov.b64 {%0, %1}, %2;" : "=f"(lo), "=f"(hi) : "l"(p));
}

// Dynamic SMEM layout (floats):
//  Phase 1/2 (staging + compute):
//   Xa  [    0,  8192)  Xa[i*128 + row] = x0[(bbase+row/16)*1024 + i*16 + row%16]
//   Xb  [ 8192, 16384)  Xb[j*128 + row] = x0[(bbase+row/16)*1024 + (row%16)*64 + j]
//   VmS [16384, 20480)  VmS[q*1024 + i*16 + v] = Vm[(k0+q)*1024 + i*16 + v]
//   VhT [20480, 24576)  VhT[q*1024 + j*16 + v] = Vh[(k0+q)*1024 + v*64 + j]
//  Phase 3 (after sync; u64 view, overwrites Xa/Xb):
//   A_u64[plane*128 + row], plane = kk*8 + vp (kk=CTA-local k, vp=v-pair)
//   B_u64 at +4096 u64 (float offset 8192)
#define SMEM_FLOATS 24576
#define SMEM_BYTES  (SMEM_FLOATS * 4)

__global__ void __launch_bounds__(NTHR, 2)
cin_kernel(const float* __restrict__ x0,
           const float* __restrict__ Vm,
           const float* __restrict__ Vh,
           float* __restrict__ out)
{
    extern __shared__ __align__(16) float smem[];
    float* Xa  = smem;
    float* Xb  = smem + 8192;
    float* VmS = smem + 16384;
    float* VhT = smem + 20480;

    const int tid   = threadIdx.x;
    const int k0    = blockIdx.x * KG;   // 16 k-groups
    const int bbase = blockIdx.y * BBLK; // 16 b-groups

    // ---- stage VmS: 4 consecutive k tiles = 4096 contiguous floats ----
    {
        const float4* src = reinterpret_cast<const float4*>(Vm + k0 * 1024);
        float4* dst = reinterpret_cast<float4*>(VmS);
        #pragma unroll
        for (int r = 0; r < 8; r++) dst[tid + r * NTHR] = src[tid + r * NTHR];
    }
    // ---- stage VhT: transpose Vh[k][v][j] -> VhT[q][j][v] ----
    {
        #pragma unroll
        for (int r = 0; r < 32; r++) {
            int idx = tid + r * NTHR;            // 0..4095
            int q   = idx >> 10;
            int rem = idx & 1023;
            int j   = rem >> 4;
            int v   = rem & 15;
            VhT[idx] = Vh[(k0 + q) * 1024 + v * 64 + j];
        }
    }
    // ---- stage Xa: Xa[i*128 + bl*16 + d] = x0[b][i][d]  (float4 both sides) ----
    {
        #pragma unroll
        for (int r = 0; r < 16; r++) {
            int idx = tid + r * NTHR;            // 0..2047 float4s
            int d4  = idx & 3;
            int bl  = (idx >> 2) & 7;
            int i   = idx >> 5;
            float4 w = *reinterpret_cast<const float4*>(
                x0 + (bbase + bl) * 1024 + i * 16 + d4 * 4);
            *reinterpret_cast<float4*>(&Xa[i * 128 + bl * 16 + d4 * 4]) = w;
        }
    }
    // ---- stage Xb: Xb[j*128 + bl*16 + d] = x0flat[b][d*64 + j] (float4 reads) ----
    {
        #pragma unroll
        for (int r = 0; r < 16; r++) {
            int idx = tid + r * NTHR;            // 0..2047
            int bl  = idx >> 8;
            int j4  = (idx >> 4) & 15;
            int d   = idx & 15;
            float4 w = *reinterpret_cast<const float4*>(
                x0 + (bbase + bl) * 1024 + d * 64 + j4 * 4);
            int base = (j4 * 4) * 128 + bl * 16 + d;
            Xb[base      ] = w.x;
            Xb[base + 128] = w.y;
            Xb[base + 256] = w.z;
            Xb[base + 384] = w.w;
        }
    }
    __syncthreads();

    const unsigned smem_b = (unsigned)__cvta_generic_to_shared(smem);

    // warp w: side = w>>1 (0 = A via Xa/VmS, 1 = B via Xb/VhT), kp = w&1.
    // k tiles handled by this warp: kk = kp*2 + {0,1} (CTA-local), k = k0 + kk.
    // lane: u = lane>>1 (rows 8u..8u+7), h = lane&1 (v-half).
    const int w    = tid >> 5;
    const int lane = tid & 31;
    const int side = w >> 1;
    const int kp   = w & 1;
    const int u    = lane >> 1;
    const int h    = lane & 1;

    const unsigned x_base  = smem_b + (unsigned)(side * 8192 * 4) + (unsigned)(u * 32);
    const unsigned v_base0 = smem_b + (unsigned)((16384 + side * 4096) * 4)
                                    + (unsigned)((kp * 2) * 4096 + h * 32);

    // acc[r][vp][kk']: r = row within lane's 8, vp = v-pair within half, kk' = k of pair
    unsigned long long acc[8][4][2];
    #pragma unroll
    for (int r = 0; r < 8; r++)
        #pragma unroll
        for (int p = 0; p < 4; p++) { acc[r][p][0] = 0ull; acc[r][p][1] = 0ull; }

    // ---- phase 2: contract over 64 indices (i for A-side, j for B-side) ----
    #pragma unroll 2
    for (int i = 0; i < 64; i++) {
        float x[8];
        unsigned xaddr = x_base + (unsigned)(i * 512);
        lds_f4(x[0], x[1], x[2], x[3], xaddr);
        lds_f4(x[4], x[5], x[6], x[7], xaddr + 16u);
        unsigned long long V0[4], V1[4];
        unsigned vaddr = v_base0 + (unsigned)(i * 64);
        lds_2x64(V0[0], V0[1], vaddr);
        lds_2x64(V0[2], V0[3], vaddr + 16u);
        lds_2x64(V1[0], V1[1], vaddr + 4096u);
        lds_2x64(V1[2], V1[3], vaddr + 4112u);
        #pragma unroll
        for (int r = 0; r < 8; r++) {
            unsigned long long xp = pack2(x[r]);
            fma2(acc[r][0][0], xp, V0[0]);
            fma2(acc[r][1][0], xp, V0[1]);
            fma2(acc[r][2][0], xp, V0[2]);
            fma2(acc[r][3][0], xp, V0[3]);
            fma2(acc[r][0][1], xp, V1[0]);
            fma2(acc[r][1][1], xp, V1[1]);
            fma2(acc[r][2][1], xp, V1[2]);
            fma2(acc[r][3][1], xp, V1[3]);
        }
    }

    __syncthreads();  // all warps done reading Xa/Xb/V before overwriting

    // ---- stash partials as u64: side region, plane = kk*8 + (h*4 + p) ----
    {
        // u64 units: side base = side*4096; addr(plane,row) = (plane*128 + row)
        unsigned sbase = smem_b + (unsigned)(side * 8192 * 4) + (unsigned)(u * 64);
        #pragma unroll
        for (int kk1 = 0; kk1 < 2; kk1++) {
            int kk = kp * 2 + kk1;
            #pragma unroll
            for (int p = 0; p < 4; p++) {
                unsigned a = sbase + (unsigned)((kk * 8 + h * 4 + p) * 1024);
                sts_2x64(a,       acc[0][p][kk1], acc[1][p][kk1]);
                sts_2x64(a + 16u, acc[2][p][kk1], acc[3][p][kk1]);
                sts_2x64(a + 32u, acc[4][p][kk1], acc[5][p][kk1]);
                sts_2x64(a + 48u, acc[6][p][kk1], acc[7][p][kk1]);
            }
        }
    }

    __syncthreads();

    // ---- phase 3: out[row, kk] = sum_v A*B, f32x2 dot (thread = row) ----
    {
        const int row = tid;  // 0..127
        const unsigned a_row = smem_b + (unsigned)(row * 8);
        const unsigned b_row = a_row + 8192u * 4u;
        #pragma unroll
        for (int kk = 0; kk < 4; kk++) {
            unsigned long long s;
            unsigned ao = a_row + (unsigned)(kk * 8 * 1024);
            unsigned bo = b_row + (unsigned)(kk * 8 * 1024);
            mul2(s, lds_u64(ao), lds_u64(bo));
            #pragma unroll
            for (int vp = 1; vp < 8; vp++) {
                unsigned long long av = lds_u64(ao + (unsigned)(vp * 1024));
                unsigned long long bv = lds_u64(bo + (unsigned)(vp * 1024));
                unsigned long long t;
                mul2(t, av, bv);
                // s += t via f32x2 add (fma with 1.0x2)
                asm("fma.rn.f32x2 %0, %1, %2, %0;"
                    : "+l"(s) : "l"(t), "l"(0x3F8000003F800000ull));
            }
            float lo, hi;
            unpack2(lo, hi, s);
            out[(bbase + (row >> 4)) * 1024 + (k0 + kk) * 16 + (row & 15)] = lo + hi;
        }
    }
}

extern "C" void kernel_launch(void* const* d_in, const int* in_sizes, int n_in,
                              void* d_out, int out_size) {
    (void)in_sizes; (void)n_in; (void)out_size;
    const float* x0 = (const float*)d_in[0];
    // d_in[1] (x_h) intentionally unused: reference recomputes it from x_0.
    const float* Vm = (const float*)d_in[2];
    const float* Vh = (const float*)d_in[3];
    float* out = (float*)d_out;

    cudaFuncSetAttribute(cin_kernel,
                         cudaFuncAttributeMaxDynamicSharedMemorySize, SMEM_BYTES);

    dim3 grid(64 / KG, 128 / BBLK);  // (16 k-groups, 16 b-groups) = 256 CTAs
    cin_kernel<<<grid, NTHR, SMEM_BYTES>>>(x0, Vm, Vh, out);
}

// round 10
// speedup vs baseline: 1.0532x; 1.0426x over previous
#include <cuda_runtime.h>

// Problem constants (fixed by setup_inputs):
// x_0  : [128, 64, 16] f32   (d_in[0])
// x_h  : [128, 64, 16] f32   (d_in[1], UNUSED — reference bug recomputes from x_0)
// Vm   : [64, 1, 64, 16] f32 (d_in[2])
// Vh   : [64, 1, 16, 64] f32 (d_in[3])
// out  : [128, 64, 16] f32
//
// out[b,k,d] = sum_v ( sum_i x0[b,i,d]*Vm[k,i,v] ) * ( sum_j x0flat[b,64d+j]*Vh[k,v,j] )
//
// R10: warp = one k (8 k per CTA); lane = 2 rows x 16 v x both sides.
// acc = 64 regs -> total <=128 regs, 2 CTAs/SM x 8 warps = 16 warps/SM.
// Per side-iter: LDS.64 x (2 wf) + 4x LDS.128 V broadcast (4 wf) vs 16 FFMA2.

#define NTHR 256
#define KG   8   // k per CTA = warps per CTA
#define BBLK 4   // batches per CTA (64 output rows)

// ---- packed f32x2 helpers ----
__device__ __forceinline__ unsigned long long pack2(float x) {
    unsigned long long r;
    asm("mov.b64 %0, {%1, %1};" : "=l"(r) : "f"(x));
    return r;
}
__device__ __forceinline__ void fma2(unsigned long long& d,
                                     unsigned long long a,
                                     unsigned long long b) {
    asm("fma.rn.f32x2 %0, %1, %2, %0;" : "+l"(d) : "l"(a), "l"(b));
}
__device__ __forceinline__ void mul2(unsigned long long& d,
                                     unsigned long long a,
                                     unsigned long long b) {
    asm("mul.rn.f32x2 %0, %1, %2;" : "=l"(d) : "l"(a), "l"(b));
}
__device__ __forceinline__ void lds_2x64(unsigned long long& p0,
                                         unsigned long long& p1,
                                         unsigned addr) {
    asm("ld.shared.v2.u64 {%0, %1}, [%2];" : "=l"(p0), "=l"(p1) : "r"(addr));
}
__device__ __forceinline__ void lds_f2(float& a, float& b, unsigned addr) {
    asm("ld.shared.v2.f32 {%0, %1}, [%2];" : "=f"(a), "=f"(b) : "r"(addr));
}
__device__ __forceinline__ void unpack2(float& lo, float& hi, unsigned long long p) {
    asm("mov.b64 {%0, %1}, %2;" : "=f"(lo), "=f"(hi) : "l"(p));
}

// Dynamic SMEM layout (floats):
//   Xa  [    0,  4096)  Xa[i*64 + row] = x0[(bbase+row/16)*1024 + i*16 + row%16]
//   Xb  [ 4096,  8192)  Xb[j*64 + row] = x0[(bbase+row/16)*1024 + (row%16)*64 + j]
//   VmS [ 8192, 16384)  VmS[q*1024 + i*16 + v] = Vm[(k0+q)*1024 + i*16 + v]
//   VhT [16384, 24576)  VhT[q*1024 + j*16 + v] = Vh[(k0+q)*1024 + v*64 + j]
#define SMEM_FLOATS 24576
#define SMEM_BYTES  (SMEM_FLOATS * 4)

__global__ void __launch_bounds__(NTHR, 2)
cin_kernel(const float* __restrict__ x0,
           const float* __restrict__ Vm,
           const float* __restrict__ Vh,
           float* __restrict__ out)
{
    extern __shared__ __align__(16) float smem[];
    float* Xa  = smem;
    float* Xb  = smem + 4096;
    float* VmS = smem + 8192;
    float* VhT = smem + 16384;

    const int tid   = threadIdx.x;
    const int k0    = blockIdx.x * KG;   // 8 k-groups
    const int bbase = blockIdx.y * BBLK; // 32 b-groups

    // ---- stage VmS: 8 consecutive k tiles = 8192 contiguous floats ----
    {
        const float4* src = reinterpret_cast<const float4*>(Vm + k0 * 1024);
        float4* dst = reinterpret_cast<float4*>(VmS);
        #pragma unroll
        for (int r = 0; r < 8; r++) dst[tid + r * NTHR] = src[tid + r * NTHR];
    }
    // ---- stage VhT: transpose Vh[k][v][j] -> VhT[q][j][v] ----
    {
        #pragma unroll
        for (int r = 0; r < 32; r++) {
            int idx = tid + r * NTHR;            // 0..8191
            int q   = idx >> 10;
            int rem = idx & 1023;
            int j   = rem >> 4;
            int v   = rem & 15;
            VhT[idx] = Vh[(k0 + q) * 1024 + v * 64 + j];
        }
    }
    // ---- stage Xa: Xa[i*64 + bl*16 + d] = x0[b][i][d]  (float4 both sides) ----
    {
        #pragma unroll
        for (int r = 0; r < 4; r++) {
            int idx = tid + r * NTHR;            // 0..1023 float4s
            int d4  = idx & 3;
            int bl  = (idx >> 2) & 3;
            int i   = idx >> 4;
            float4 w = *reinterpret_cast<const float4*>(
                x0 + (bbase + bl) * 1024 + i * 16 + d4 * 4);
            *reinterpret_cast<float4*>(&Xa[i * 64 + bl * 16 + d4 * 4]) = w;
        }
    }
    // ---- stage Xb: Xb[j*64 + bl*16 + d] = x0flat[b][d*64 + j] (float4 reads) ----
    {
        #pragma unroll
        for (int r = 0; r < 4; r++) {
            int idx = tid + r * NTHR;            // 0..1023
            int bl  = idx >> 8;
            int j4  = (idx >> 4) & 15;
            int d   = idx & 15;
            float4 w = *reinterpret_cast<const float4*>(
                x0 + (bbase + bl) * 1024 + d * 64 + j4 * 4);
            int base = j4 * 256 + bl * 16 + d;
            Xb[base      ] = w.x;
            Xb[base +  64] = w.y;
            Xb[base + 128] = w.z;
            Xb[base + 192] = w.w;
        }
    }
    __syncthreads();

    const unsigned smem_b = (unsigned)__cvta_generic_to_shared(smem);

    // warp q = tid>>5 -> k = k0+q; lane u = tid&31 -> rows 2u, 2u+1 (of 64)
    const int q = tid >> 5;
    const int u = tid & 31;

    const unsigned xa_r = smem_b + (unsigned)(u * 8);
    const unsigned xb_r = smem_b + 4096u * 4u + (unsigned)(u * 8);
    const unsigned vm_q = smem_b + 8192u * 4u + (unsigned)(q * 4096);
    const unsigned vh_q = smem_b + 16384u * 4u + (unsigned)(q * 4096);

    unsigned long long A[2][8], B[2][8];
    #pragma unroll
    for (int p = 0; p < 8; p++) {
        A[0][p] = 0ull; A[1][p] = 0ull;
        B[0][p] = 0ull; B[1][p] = 0ull;
    }

    // ---- A side: contract over i with Vm ----
    #pragma unroll 2
    for (int i = 0; i < 64; i++) {
        float xl, xh;
        lds_f2(xl, xh, xa_r + (unsigned)(i * 256));
        unsigned long long V[8];
        unsigned va = vm_q + (unsigned)(i * 64);
        lds_2x64(V[0], V[1], va);
        lds_2x64(V[2], V[3], va + 16u);
        lds_2x64(V[4], V[5], va + 32u);
        lds_2x64(V[6], V[7], va + 48u);
        unsigned long long xp0 = pack2(xl);
        unsigned long long xp1 = pack2(xh);
        #pragma unroll
        for (int p = 0; p < 8; p++) {
            fma2(A[0][p], xp0, V[p]);
            fma2(A[1][p], xp1, V[p]);
        }
    }
    // ---- B side: contract over j with Vh^T ----
    #pragma unroll 2
    for (int j = 0; j < 64; j++) {
        float xl, xh;
        lds_f2(xl, xh, xb_r + (unsigned)(j * 256));
        unsigned long long V[8];
        unsigned va = vh_q + (unsigned)(j * 64);
        lds_2x64(V[0], V[1], va);
        lds_2x64(V[2], V[3], va + 16u);
        lds_2x64(V[4], V[5], va + 32u);
        lds_2x64(V[6], V[7], va + 48u);
        unsigned long long xp0 = pack2(xl);
        unsigned long long xp1 = pack2(xh);
        #pragma unroll
        for (int p = 0; p < 8; p++) {
            fma2(B[0][p], xp0, V[p]);
            fma2(B[1][p], xp1, V[p]);
        }
    }

    // ---- dot over v (elementwise f32x2 product-accumulate), store 2 rows ----
    #pragma unroll
    for (int rr = 0; rr < 2; rr++) {
        unsigned long long s;
        mul2(s, A[rr][0], B[rr][0]);
        #pragma unroll
        for (int p = 1; p < 8; p++) fma2(s, A[rr][p], B[rr][p]);
        float lo, hi;
        unpack2(lo, hi, s);
        int row = u * 2 + rr;                 // 0..63
        out[(bbase + (row >> 4)) * 1024 + (k0 + q) * 16 + (row & 15)] = lo + hi;
    }
}

extern "C" void kernel_launch(void* const* d_in, const int* in_sizes, int n_in,
                              void* d_out, int out_size) {
    (void)in_sizes; (void)n_in; (void)out_size;
    const float* x0 = (const float*)d_in[0];
    // d_in[1] (x_h) intentionally unused: reference recomputes it from x_0.
    const float* Vm = (const float*)d_in[2];
    const float* Vh = (const float*)d_in[3];
    float* out = (float*)d_out;

    cudaFuncSetAttribute(cin_kernel,
                         cudaFuncAttributeMaxDynamicSharedMemorySize, SMEM_BYTES);

    dim3 grid(64 / KG, 128 / BBLK);  // (8 k-groups, 32 b-groups) = 256 CTAs
    cin_kernel<<<grid, NTHR, SMEM_BYTES>>>(x0, Vm, Vh, out);
}

// round 11
// speedup vs baseline: 1.1000x; 1.0444x over previous
#include <cuda_runtime.h>

// Problem constants (fixed by setup_inputs):
// x_0  : [128, 64, 16] f32   (d_in[0])
// x_h  : [128, 64, 16] f32   (d_in[1], UNUSED — reference bug recomputes from x_0)
// Vm   : [64, 1, 64, 16] f32 (d_in[2])
// Vh   : [64, 1, 16, 64] f32 (d_in[3])
// out  : [128, 64, 16] f32
//
// out[b,k,d] = sum_v ( sum_i x0[b,i,d]*Vm[k,i,v] ) * ( sum_j x0flat[b,64d+j]*Vh[k,v,j] )
//
// R11: warp = (side, k). lane = (u = 8-row group, h = v-half).
// acc = 8 rows x 4 v-pairs = 32 u64 = 64 regs. 48B smem writeback per
// warp-FFMA2 (crossbar 14.2K cyc/SM vs FMA 16.4K cyc/SM). Partials exchanged
// via smem as u64, f32x2 dot in phase 3.

#define NTHR 256
#define KG   4   // k per CTA
#define BBLK 8   // batches per CTA (128 output rows)

// ---- packed f32x2 helpers ----
__device__ __forceinline__ unsigned long long pack2(float x) {
    unsigned long long r;
    asm("mov.b64 %0, {%1, %1};" : "=l"(r) : "f"(x));
    return r;
}
__device__ __forceinline__ void fma2(unsigned long long& d,
                                     unsigned long long a,
                                     unsigned long long b) {
    asm("fma.rn.f32x2 %0, %1, %2, %0;" : "+l"(d) : "l"(a), "l"(b));
}
__device__ __forceinline__ void mul2(unsigned long long& d,
                                     unsigned long long a,
                                     unsigned long long b) {
    asm("mul.rn.f32x2 %0, %1, %2;" : "=l"(d) : "l"(a), "l"(b));
}
__device__ __forceinline__ void lds_2x64(unsigned long long& p0,
                                         unsigned long long& p1,
                                         unsigned addr) {
    asm("ld.shared.v2.u64 {%0, %1}, [%2];" : "=l"(p0), "=l"(p1) : "r"(addr));
}
__device__ __forceinline__ void lds_f4(float& a, float& b, float& c, float& d,
                                       unsigned addr) {
    asm("ld.shared.v4.f32 {%0, %1, %2, %3}, [%4];"
        : "=f"(a), "=f"(b), "=f"(c), "=f"(d) : "r"(addr));
}
__device__ __forceinline__ void sts_2x64(unsigned addr,
                                         unsigned long long a,
                                         unsigned long long b) {
    asm("st.shared.v2.u64 [%0], {%1, %2};" :: "r"(addr), "l"(a), "l"(b));
}
__device__ __forceinline__ unsigned long long lds_u64(unsigned addr) {
    unsigned long long r;
    asm("ld.shared.u64 %0, [%1];" : "=l"(r) : "r"(addr));
    return r;
}
__device__ __forceinline__ void unpack2(float& lo, float& hi, unsigned long long p) {
    asm("mov.b64 {%0, %1}, %2;" : "=f"(lo), "=f"(hi) : "l"(p));
}

// Dynamic SMEM layout (floats):
//  Phase 1/2 (staging + compute):
//   Xa  [    0,  8192)  Xa[i*128 + row] = x0[(bbase+row/16)*1024 + i*16 + row%16]
//   Xb  [ 8192, 16384)  Xb[j*128 + row] = x0[(bbase+row/16)*1024 + (row%16)*64 + j]
//   VmS [16384, 20480)  VmS[q*1024 + i*16 + v] = Vm[(k0+q)*1024 + i*16 + v]
//   VhT [20480, 24576)  VhT[q*1024 + j*16 + v] = Vh[(k0+q)*1024 + v*64 + j]
//  Phase 3 (after sync; u64 view, overwrites Xa/Xb):
//   A_u64[plane*128 + row], plane = q*8 + h*4 + p  (q=CTA-local k, p=v-pair)
//   B_u64 at float offset 8192 (u64 offset 4096)
#define SMEM_FLOATS 24576
#define SMEM_BYTES  (SMEM_FLOATS * 4)

__global__ void __launch_bounds__(NTHR, 2)
cin_kernel(const float* __restrict__ x0,
           const float* __restrict__ Vm,
           const float* __restrict__ Vh,
           float* __restrict__ out)
{
    extern __shared__ __align__(16) float smem[];
    float* Xa  = smem;
    float* Xb  = smem + 8192;
    float* VmS = smem + 16384;
    float* VhT = smem + 20480;

    const int tid   = threadIdx.x;
    const int k0    = blockIdx.x * KG;   // 16 k-groups
    const int bbase = blockIdx.y * BBLK; // 16 b-groups

    // ---- stage VmS: 4 consecutive k tiles = 4096 contiguous floats ----
    {
        const float4* src = reinterpret_cast<const float4*>(Vm + k0 * 1024);
        float4* dst = reinterpret_cast<float4*>(VmS);
        #pragma unroll
        for (int r = 0; r < 4; r++) dst[tid + r * NTHR] = src[tid + r * NTHR];
    }
    // ---- stage VhT: transpose Vh[k][v][j] -> VhT[q][j][v] ----
    {
        #pragma unroll
        for (int r = 0; r < 16; r++) {
            int idx = tid + r * NTHR;            // 0..4095
            int q   = idx >> 10;
            int rem = idx & 1023;
            int j   = rem >> 4;
            int v   = rem & 15;
            VhT[idx] = Vh[(k0 + q) * 1024 + v * 64 + j];
        }
    }
    // ---- stage Xa: Xa[i*128 + bl*16 + d] = x0[b][i][d]  (float4 both sides) ----
    {
        #pragma unroll
        for (int r = 0; r < 8; r++) {
            int idx = tid + r * NTHR;            // 0..2047 float4s
            int d4  = idx & 3;
            int bl  = (idx >> 2) & 7;
            int i   = idx >> 5;
            float4 w = *reinterpret_cast<const float4*>(
                x0 + (bbase + bl) * 1024 + i * 16 + d4 * 4);
            *reinterpret_cast<float4*>(&Xa[i * 128 + bl * 16 + d4 * 4]) = w;
        }
    }
    // ---- stage Xb: Xb[j*128 + bl*16 + d] = x0flat[b][d*64 + j] (float4 reads) ----
    {
        #pragma unroll
        for (int r = 0; r < 8; r++) {
            int idx = tid + r * NTHR;            // 0..2047
            int bl  = idx >> 8;
            int j4  = (idx >> 4) & 15;
            int d   = idx & 15;
            float4 w = *reinterpret_cast<const float4*>(
                x0 + (bbase + bl) * 1024 + d * 64 + j4 * 4);
            int base = (j4 * 4) * 128 + bl * 16 + d;
            Xb[base      ] = w.x;
            Xb[base + 128] = w.y;
            Xb[base + 256] = w.z;
            Xb[base + 384] = w.w;
        }
    }
    __syncthreads();

    const unsigned smem_b = (unsigned)__cvta_generic_to_shared(smem);

    // warp w: side = w>>2 (0 = A via Xa/VmS, 1 = B via Xb/VhT), q = w&3 -> k = k0+q.
    // lane: u = lane>>1 (rows 8u..8u+7), h = lane&1 (v-half).
    const int w    = tid >> 5;
    const int lane = tid & 31;
    const int side = w >> 2;
    const int q    = w & 3;
    const int u    = lane >> 1;
    const int h    = lane & 1;

    const unsigned x_base = smem_b + (unsigned)(side * 8192 * 4) + (unsigned)(u * 32);
    const unsigned v_base = smem_b + (unsigned)((16384 + side * 4096) * 4)
                                   + (unsigned)(q * 4096 + h * 32);

    // acc[r][p]: r = row within lane's 8, p = v-pair within half
    unsigned long long acc[8][4];
    #pragma unroll
    for (int r = 0; r < 8; r++)
        #pragma unroll
        for (int p = 0; p < 4; p++) acc[r][p] = 0ull;

    // ---- phase 2: contract over 64 indices (i for A-side, j for B-side) ----
    #pragma unroll 4
    for (int i = 0; i < 64; i++) {
        float x[8];
        unsigned xaddr = x_base + (unsigned)(i * 512);
        lds_f4(x[0], x[1], x[2], x[3], xaddr);
        lds_f4(x[4], x[5], x[6], x[7], xaddr + 16u);
        unsigned long long V[4];
        unsigned vaddr = v_base + (unsigned)(i * 64);
        lds_2x64(V[0], V[1], vaddr);
        lds_2x64(V[2], V[3], vaddr + 16u);
        #pragma unroll
        for (int r = 0; r < 8; r++) {
            unsigned long long xp = pack2(x[r]);
            fma2(acc[r][0], xp, V[0]);
            fma2(acc[r][1], xp, V[1]);
            fma2(acc[r][2], xp, V[2]);
            fma2(acc[r][3], xp, V[3]);
        }
    }

    __syncthreads();  // all warps done reading Xa/Xb/V before overwriting

    // ---- stash partials as u64: side region, plane = q*8 + h*4 + p ----
    {
        // u64 addressing: addr(plane,row) = side*32768B + plane*1024B + row*8B
        unsigned sbase = smem_b + (unsigned)(side * 8192 * 4)
                                + (unsigned)((q * 8 + h * 4) * 1024)
                                + (unsigned)(u * 64);
        #pragma unroll
        for (int p = 0; p < 4; p++) {
            unsigned a = sbase + (unsigned)(p * 1024);
            sts_2x64(a,       acc[0][p], acc[1][p]);
            sts_2x64(a + 16u, acc[2][p], acc[3][p]);
            sts_2x64(a + 32u, acc[4][p], acc[5][p]);
            sts_2x64(a + 48u, acc[6][p], acc[7][p]);
        }
    }

    __syncthreads();

    // ---- phase 3: out[row, k] = sum_v A*B, f32x2 dot ----
    // thread = (row = tid&127, kh = tid>>7); each handles k = kh*2, kh*2+1
    {
        const int row = tid & 127;
        const int kh  = tid >> 7;
        const unsigned a_row = smem_b + (unsigned)(row * 8);
        const unsigned b_row = a_row + 8192u * 4u;
        #pragma unroll
        for (int kx = 0; kx < 2; kx++) {
            int k = kh * 2 + kx;
            unsigned ao = a_row + (unsigned)(k * 8 * 1024);
            unsigned bo = b_row + (unsigned)(k * 8 * 1024);
            unsigned long long s;
            mul2(s, lds_u64(ao), lds_u64(bo));
            #pragma unroll
            for (int vp = 1; vp < 8; vp++) {
                unsigned long long av = lds_u64(ao + (unsigned)(vp * 1024));
                unsigned long long bv = lds_u64(bo + (unsigned)(vp * 1024));
                unsigned long long t;
                mul2(t, av, bv);
                asm("fma.rn.f32x2 %0, %1, %2, %0;"
                    : "+l"(s) : "l"(t), "l"(0x3F8000003F800000ull));
            }
            float lo, hi;
            unpack2(lo, hi, s);
            out[(bbase + (row >> 4)) * 1024 + (k0 + k) * 16 + (row & 15)] = lo + hi;
        }
    }
}

extern "C" void kernel_launch(void* const* d_in, const int* in_sizes, int n_in,
                              void* d_out, int out_size) {
    (void)in_sizes; (void)n_in; (void)out_size;
    const float* x0 = (const float*)d_in[0];
    // d_in[1] (x_h) intentionally unused: reference recomputes it from x_0.
    const float* Vm = (const float*)d_in[2];
    const float* Vh = (const float*)d_in[3];
    float* out = (float*)d_out;

    cudaFuncSetAttribute(cin_kernel,
                         cudaFuncAttributeMaxDynamicSharedMemorySize, SMEM_BYTES);

    dim3 grid(64 / KG, 128 / BBLK);  // (16 k-groups, 16 b-groups) = 256 CTAs
    cin_kernel<<<grid, NTHR, SMEM_BYTES>>>(x0, Vm, Vh, out);
}